// round 4
// baseline (speedup 1.0000x reference)
#include <cuda_runtime.h>

// ProjectionSimToPointCloud: image (2048, 8192, 4) f32 -> points (2048*8192, 3) f32
//   depth = image[..., 3]
//   pitch(i) = (1 - i/h) * (FOV_UP + |FOV_DOWN|) - |FOV_DOWN|
//   yaw(j)   = j/w * 2*pi - pi
//   x = depth*cos(yaw), y = -depth*sin(yaw), z = depth*sin(pitch)
//
// Single fused kernel, 8 pixels/thread:
//  - 8 front-batched __ldcs depth loads (MLP_p1=8, streaming/evict-first)
//  - inline MUFU trig (hidden under the DRAM-bound window)
//  - 6x STG.128 streaming stores (96B contiguous per thread)

#define IMG_H 2048
#define IMG_W 8192
#define PPT   8   // pixels per thread

__global__ void __launch_bounds__(256) project_fused8(
    const float* __restrict__ img,    // (H*W*4) floats, depth at 4k+3
    float* __restrict__ out)          // (H*W*3) floats
{
    const int t  = blockIdx.x * blockDim.x + threadIdx.x;
    const int p0 = t * PPT;                     // first pixel (multiple of 8)
    const int j0 = p0 & (IMG_W - 1);            // row not crossed (W % 8 == 0)
    const int i  = p0 >> 13;                    // log2(IMG_W) = 13

    // 8 independent streaming depth loads, front-batched.
    float d[PPT];
#pragma unroll
    for (int m = 0; m < PPT; m++)
        d[m] = __ldcs(img + (p0 + m) * 4 + 3);

    // yaw(j) = j * (2*pi/W) - pi
    const float YAW_STEP = 7.6699039394282161e-4f;   // 2*pi/8192
    const float PI_F     = 3.14159265358979323846f;
    const float yaw0 = (float)j0 * YAW_STEP - PI_F;

    float s[PPT], c[PPT];
#pragma unroll
    for (int m = 0; m < PPT; m++)
        __sincosf(yaw0 + (float)m * YAW_STEP, &s[m], &c[m]);

    // pitch(i) = FOV_UP - i * (span/H); warp-uniform.
    const float PITCH_A = 0.26179938779914943654f;   // FOV_UP in radians
    const float PITCH_B = 2.5566346454293863e-4f;    // (30deg in rad)/2048
    const float sp = __sinf(PITCH_A - (float)i * PITCH_B);

    // 24 output floats = 96 contiguous bytes, 16B-aligned -> 6x STG.128 (streaming).
    float o[PPT * 3];
#pragma unroll
    for (int m = 0; m < PPT; m++) {
        o[3 * m + 0] =  d[m] * c[m];
        o[3 * m + 1] = -d[m] * s[m];
        o[3 * m + 2] =  d[m] * sp;
    }

    float4* outv = reinterpret_cast<float4*>(out) + t * (PPT * 3 / 4);
#pragma unroll
    for (int v = 0; v < PPT * 3 / 4; v++) {
        float4 w = make_float4(o[4 * v + 0], o[4 * v + 1], o[4 * v + 2], o[4 * v + 3]);
        __stcs(outv + v, w);
    }
}

extern "C" void kernel_launch(void* const* d_in, const int* in_sizes, int n_in,
                              void* d_out, int out_size) {
    const float* img = (const float*)d_in[0];
    float* out = (float*)d_out;

    const int n_threads = (IMG_H * IMG_W) / PPT;   // 2,097,152
    project_fused8<<<n_threads / 256, 256>>>(img, out);
}